// round 1
// baseline (speedup 1.0000x reference)
#include <cuda_runtime.h>
#include <math.h>

// Problem constants
#define BB   8
#define CC   512
#define HHN  64
#define WWN  64
#define NN   4096            // H*W
#define MM   (BB*NN)         // 32768 tokens
#define NHH  8
#define DDIM 64
#define EPSV 1e-5f
#define SCALEV 0.125f        // 64^-0.5

#define MODE_PLAIN 0
#define MODE_ROPE  1
#define MODE_OUT   2

// Scratch (device globals: allocation-free rule)
__device__ float g_qln [MM*CC];
__device__ float g_kvln[MM*CC];
__device__ float g_Qb  [MM*CC];
__device__ float g_Kb  [MM*CC];
__device__ float g_Vb  [MM*CC];
__device__ float g_AO  [MM*CC];
__device__ float g_rope[NN*32*2];   // [n][p][{sin,cos}]

// ---------------------------------------------------------------------------
// LayerNorm over C at each spatial position. Input NCHW, output (B*N, C).
// One block = 16 positions. Tile staged in smem so NCHW reads stay coalesced.
// ---------------------------------------------------------------------------
__global__ void __launch_bounds__(256) ln_kernel(const float* __restrict__ x,
                                                 const float* __restrict__ g,
                                                 const float* __restrict__ bln,
                                                 float* __restrict__ out)
{
    __shared__ float tile[CC][17];
    __shared__ float s_mu[16], s_rs[16];

    int m0   = blockIdx.x * 16;        // global token index base
    int bimg = m0 / NN;
    int n0   = m0 % NN;
    const float* xb = x + (size_t)bimg * CC * NN + n0;

    for (int idx = threadIdx.x; idx < CC * 16; idx += 256) {
        int c = idx >> 4, p = idx & 15;
        tile[c][p] = xb[(size_t)c * NN + p];
    }
    __syncthreads();

    int p = threadIdx.x >> 4;          // position within tile (16 threads each)
    int l = threadIdx.x & 15;
    float sum = 0.f, sq = 0.f;
    #pragma unroll
    for (int i = 0; i < 32; i++) {
        float v = tile[l + 16 * i][p];
        sum += v; sq += v * v;
    }
    #pragma unroll
    for (int o = 8; o > 0; o >>= 1) {
        sum += __shfl_xor_sync(0xffffffffu, sum, o);
        sq  += __shfl_xor_sync(0xffffffffu, sq,  o);
    }
    if (l == 0) {
        float mu  = sum * (1.f / 512.f);
        float var = sq * (1.f / 512.f) - mu * mu;
        s_mu[p] = mu;
        s_rs[p] = rsqrtf(var + EPSV);
    }
    __syncthreads();

    for (int idx = threadIdx.x; idx < CC * 16; idx += 256) {
        int pp = idx >> 9, c = idx & 511;
        float v = (tile[c][pp] - s_mu[pp]) * s_rs[pp] * g[c] + bln[c];
        out[(size_t)(m0 + pp) * CC + c] = v;
    }
}

// ---------------------------------------------------------------------------
// RoPE sin/cos table, fp32 math matching the reference.
// ---------------------------------------------------------------------------
__global__ void rope_kernel(float* __restrict__ rope)
{
    int idx = blockIdx.x * 256 + threadIdx.x;
    if (idx >= NN * 32) return;
    int n = idx >> 5, pp = idx & 31;
    float inv = 1.f / powf(10000.f, (float)(2 * pp) / 64.f);
    float ang = (float)n * inv;
    rope[idx * 2]     = sinf(ang);
    rope[idx * 2 + 1] = cosf(ang);
}

// ---------------------------------------------------------------------------
// GEMM: C[m,n] = sum_k A[m,k]*W[n,k] + bias[n]   (M=32768, N=512, K=512)
// 128x128 block tile, 8x8 per-thread micro-tile, Ktile=16.
// mode=ROPE: fused RoPE on the output (Q,K projections).
// mode=OUT : fused residual add + NCHW-transposed store.
// ---------------------------------------------------------------------------
__global__ void __launch_bounds__(256) gemm_kernel(
    const float* __restrict__ A, const float* __restrict__ Wm,
    const float* __restrict__ bias, float* __restrict__ Cout,
    const float* __restrict__ rope, const float* __restrict__ resid,
    int mode)
{
    __shared__ float As[16][132];
    __shared__ float Bs[16][132];

    int m0  = blockIdx.y * 128;
    int n0  = blockIdx.x * 128;
    int tid = threadIdx.x;
    int tx  = tid & 15, ty = tid >> 4;

    float acc[8][8];
    #pragma unroll
    for (int i = 0; i < 8; i++)
        #pragma unroll
        for (int j = 0; j < 8; j++) acc[i][j] = 0.f;

    for (int kt = 0; kt < 512; kt += 16) {
        #pragma unroll
        for (int hh = 0; hh < 2; hh++) {
            int f = tid + hh * 256;
            int r = f >> 2, q = f & 3;
            float4 av = *(const float4*)(A  + (size_t)(m0 + r) * 512 + kt + q * 4);
            As[q*4+0][r] = av.x; As[q*4+1][r] = av.y;
            As[q*4+2][r] = av.z; As[q*4+3][r] = av.w;
            float4 bv = *(const float4*)(Wm + (size_t)(n0 + r) * 512 + kt + q * 4);
            Bs[q*4+0][r] = bv.x; Bs[q*4+1][r] = bv.y;
            Bs[q*4+2][r] = bv.z; Bs[q*4+3][r] = bv.w;
        }
        __syncthreads();

        #pragma unroll
        for (int k = 0; k < 16; k++) {
            float a[8], b[8];
            *(float4*)(a)     = *(const float4*)&As[k][ty * 8];
            *(float4*)(a + 4) = *(const float4*)&As[k][ty * 8 + 4];
            *(float4*)(b)     = *(const float4*)&Bs[k][tx * 8];
            *(float4*)(b + 4) = *(const float4*)&Bs[k][tx * 8 + 4];
            #pragma unroll
            for (int i = 0; i < 8; i++)
                #pragma unroll
                for (int j = 0; j < 8; j++)
                    acc[i][j] += a[i] * b[j];
        }
        __syncthreads();
    }

    // bias
    float bvv[8];
    #pragma unroll
    for (int j = 0; j < 8; j++) bvv[j] = bias[n0 + tx * 8 + j];
    #pragma unroll
    for (int i = 0; i < 8; i++)
        #pragma unroll
        for (int j = 0; j < 8; j++) acc[i][j] += bvv[j];

    if (mode == MODE_ROPE) {
        int cbase = n0 + tx * 8;
        int p0 = (cbase & 63) >> 1;            // pair index within head
        #pragma unroll
        for (int i = 0; i < 8; i++) {
            int npos = (m0 + ty * 8 + i) & (NN - 1);
            const float* rp = rope + (size_t)npos * 64;
            #pragma unroll
            for (int jp = 0; jp < 4; jp++) {
                float s = rp[(p0 + jp) * 2];
                float c = rp[(p0 + jp) * 2 + 1];
                float x0 = acc[i][2 * jp], x1 = acc[i][2 * jp + 1];
                acc[i][2 * jp]     = x0 * c - x1 * s;
                acc[i][2 * jp + 1] = x0 * s + x1 * c;
            }
        }
    }

    if (mode == MODE_OUT) {
        // residual add (layernormed q), then NCHW-transposed store
        #pragma unroll
        for (int i = 0; i < 8; i++) {
            const float4* rr = (const float4*)(resid + (size_t)(m0 + ty * 8 + i) * 512 + n0 + tx * 8);
            float4 r0 = rr[0], r1 = rr[1];
            acc[i][0] += r0.x; acc[i][1] += r0.y; acc[i][2] += r0.z; acc[i][3] += r0.w;
            acc[i][4] += r1.x; acc[i][5] += r1.y; acc[i][6] += r1.z; acc[i][7] += r1.w;
        }
        int bimg  = m0 >> 12;                  // 128-row tiles never cross images
        int nbase = (m0 & (NN - 1)) + ty * 8;
        #pragma unroll
        for (int j = 0; j < 8; j++) {
            int co = n0 + tx * 8 + j;
            float* op = Cout + (size_t)bimg * CC * NN + (size_t)co * NN + nbase;
            float4 v0 = make_float4(acc[0][j], acc[1][j], acc[2][j], acc[3][j]);
            float4 v1 = make_float4(acc[4][j], acc[5][j], acc[6][j], acc[7][j]);
            *(float4*)op       = v0;
            *(float4*)(op + 4) = v1;
        }
    } else {
        #pragma unroll
        for (int i = 0; i < 8; i++) {
            float* op = Cout + (size_t)(m0 + ty * 8 + i) * 512 + n0 + tx * 8;
            *(float4*)op       = make_float4(acc[i][0], acc[i][1], acc[i][2], acc[i][3]);
            *(float4*)(op + 4) = make_float4(acc[i][4], acc[i][5], acc[i][6], acc[i][7]);
        }
    }
}

// ---------------------------------------------------------------------------
// Window attention: one block per (head, window). Ws=64, D=64.
// Q, V kept row-major in smem; K stored transposed (Kt[d][j]) so the
// lane-contiguous index hits the last smem dim in both GEMM phases.
// ---------------------------------------------------------------------------
#define ATTN_SMEM (4 * 64 * 68 * 4)

__global__ void __launch_bounds__(256) attn_kernel(
    const float* __restrict__ Q, const float* __restrict__ K,
    const float* __restrict__ V, const float* __restrict__ bt,
    float* __restrict__ O)
{
    extern __shared__ float sm[];
    float* Qs = sm;                 // [64][68]
    float* Kt = sm + 64 * 68;       // [64][68]  Kt[d][j]
    float* Vs = sm + 2 * 64 * 68;   // [64][68]
    float* S  = sm + 3 * 64 * 68;   // [64][68]
    __shared__ float tb[232];       // bias table slice for this head

    int bi  = blockIdx.x;
    int h   = bi >> 9;
    int rem = bi & 511;
    int b   = rem >> 6;
    int hn  = (rem >> 3) & 7;
    int wn  = rem & 7;
    int tid = threadIdx.x;

    for (int t = tid; t < 225; t += 256) tb[t] = bt[t * NHH + h];

    size_t base = ((size_t)b * NN) * CC + (size_t)h * DDIM;

    for (int f = tid; f < 1024; f += 256) {
        int s  = f >> 4, dq = f & 15;
        int wh = s >> 3, ww = s & 7;
        int n  = (hn * 8 + wh) * 64 + wn * 8 + ww;
        size_t ga = base + (size_t)n * CC + dq * 4;
        float4 qv = *(const float4*)(Q + ga);
        *(float4*)&Qs[s * 68 + dq * 4] = qv;
        float4 kv = *(const float4*)(K + ga);
        Kt[(dq * 4 + 0) * 68 + s] = kv.x;
        Kt[(dq * 4 + 1) * 68 + s] = kv.y;
        Kt[(dq * 4 + 2) * 68 + s] = kv.z;
        Kt[(dq * 4 + 3) * 68 + s] = kv.w;
        float4 vv = *(const float4*)(V + ga);
        *(float4*)&Vs[s * 68 + dq * 4] = vv;
    }
    __syncthreads();

    int tc = tid & 15, tr = tid >> 4;
    int r0 = tr * 4, c0 = tc * 4;

    // S = Q K^T
    float acc[4][4] = {};
    for (int d = 0; d < 64; d += 4) {
        float4 kf[4];
        #pragma unroll
        for (int u = 0; u < 4; u++) kf[u] = *(const float4*)&Kt[(d + u) * 68 + c0];
        #pragma unroll
        for (int ii = 0; ii < 4; ii++) {
            float4 qf = *(const float4*)&Qs[(r0 + ii) * 68 + d];
            acc[ii][0] += qf.x*kf[0].x + qf.y*kf[1].x + qf.z*kf[2].x + qf.w*kf[3].x;
            acc[ii][1] += qf.x*kf[0].y + qf.y*kf[1].y + qf.z*kf[2].y + qf.w*kf[3].y;
            acc[ii][2] += qf.x*kf[0].z + qf.y*kf[1].z + qf.z*kf[2].z + qf.w*kf[3].z;
            acc[ii][3] += qf.x*kf[0].w + qf.y*kf[1].w + qf.z*kf[2].w + qf.w*kf[3].w;
        }
    }

    // scale + relative-position bias -> S
    #pragma unroll
    for (int ii = 0; ii < 4; ii++) {
        int i = r0 + ii; int ih = i >> 3, iw = i & 7;
        #pragma unroll
        for (int jj = 0; jj < 4; jj++) {
            int j = c0 + jj; int jh = j >> 3, jw = j & 7;
            int ridx = (ih - jh + 7) * 15 + (iw - jw + 7);
            S[i * 68 + j] = acc[ii][jj] * SCALEV + tb[ridx];
        }
    }
    __syncthreads();

    // softmax per row: 4 lanes per row, 16 cols each
    {
        int r = tid >> 2, qg = tid & 3;
        float* row = S + r * 68 + qg * 16;
        float mx = -INFINITY;
        #pragma unroll
        for (int j = 0; j < 16; j++) mx = fmaxf(mx, row[j]);
        mx = fmaxf(mx, __shfl_xor_sync(0xffffffffu, mx, 1));
        mx = fmaxf(mx, __shfl_xor_sync(0xffffffffu, mx, 2));
        float e[16], sum = 0.f;
        #pragma unroll
        for (int j = 0; j < 16; j++) { e[j] = expf(row[j] - mx); sum += e[j]; }
        sum += __shfl_xor_sync(0xffffffffu, sum, 1);
        sum += __shfl_xor_sync(0xffffffffu, sum, 2);
        float inv = 1.f / sum;
        #pragma unroll
        for (int j = 0; j < 16; j++) row[j] = e[j] * inv;
    }
    __syncthreads();

    // O = P V
    float oacc[4][4] = {};
    for (int j = 0; j < 64; j += 4) {
        float4 vf[4];
        #pragma unroll
        for (int u = 0; u < 4; u++) vf[u] = *(const float4*)&Vs[(j + u) * 68 + c0];
        #pragma unroll
        for (int ii = 0; ii < 4; ii++) {
            float4 pf = *(const float4*)&S[(r0 + ii) * 68 + j];
            oacc[ii][0] += pf.x*vf[0].x + pf.y*vf[1].x + pf.z*vf[2].x + pf.w*vf[3].x;
            oacc[ii][1] += pf.x*vf[0].y + pf.y*vf[1].y + pf.z*vf[2].y + pf.w*vf[3].y;
            oacc[ii][2] += pf.x*vf[0].z + pf.y*vf[1].z + pf.z*vf[2].z + pf.w*vf[3].z;
            oacc[ii][3] += pf.x*vf[0].w + pf.y*vf[1].w + pf.z*vf[2].w + pf.w*vf[3].w;
        }
    }

    #pragma unroll
    for (int ii = 0; ii < 4; ii++) {
        int s  = r0 + ii;
        int wh = s >> 3, ww = s & 7;
        int n  = (hn * 8 + wh) * 64 + wn * 8 + ww;
        *(float4*)(O + base + (size_t)n * CC + c0) =
            make_float4(oacc[ii][0], oacc[ii][1], oacc[ii][2], oacc[ii][3]);
    }
}

// ---------------------------------------------------------------------------
extern "C" void kernel_launch(void* const* d_in, const int* in_sizes, int n_in,
                              void* d_out, int out_size)
{
    const float* q    = (const float*)d_in[0];
    const float* kv   = (const float*)d_in[1];
    const float* g_q  = (const float*)d_in[2];
    const float* b_q  = (const float*)d_in[3];
    const float* g_kv = (const float*)d_in[4];
    const float* b_kv = (const float*)d_in[5];
    const float* Wq   = (const float*)d_in[6];
    const float* bq   = (const float*)d_in[7];
    const float* Wk   = (const float*)d_in[8];
    const float* bk   = (const float*)d_in[9];
    const float* Wv   = (const float*)d_in[10];
    const float* bv   = (const float*)d_in[11];
    const float* Wo   = (const float*)d_in[12];
    const float* bo   = (const float*)d_in[13];
    const float* bt   = (const float*)d_in[14];
    float* out = (float*)d_out;

    void *p_qln, *p_kvln, *p_Q, *p_K, *p_V, *p_AO, *p_rope;
    cudaGetSymbolAddress(&p_qln,  g_qln);
    cudaGetSymbolAddress(&p_kvln, g_kvln);
    cudaGetSymbolAddress(&p_Q,    g_Qb);
    cudaGetSymbolAddress(&p_K,    g_Kb);
    cudaGetSymbolAddress(&p_V,    g_Vb);
    cudaGetSymbolAddress(&p_AO,   g_AO);
    cudaGetSymbolAddress(&p_rope, g_rope);

    cudaFuncSetAttribute(attn_kernel, cudaFuncAttributeMaxDynamicSharedMemorySize, ATTN_SMEM);

    ln_kernel<<<MM / 16, 256>>>(q,  g_q,  b_q,  (float*)p_qln);
    ln_kernel<<<MM / 16, 256>>>(kv, g_kv, b_kv, (float*)p_kvln);
    rope_kernel<<<(NN * 32 + 255) / 256, 256>>>((float*)p_rope);

    dim3 gg(4, 256);
    gemm_kernel<<<gg, 256>>>((const float*)p_qln,  Wq, bq, (float*)p_Q,
                             (const float*)p_rope, nullptr, MODE_ROPE);
    gemm_kernel<<<gg, 256>>>((const float*)p_kvln, Wk, bk, (float*)p_K,
                             (const float*)p_rope, nullptr, MODE_ROPE);
    gemm_kernel<<<gg, 256>>>((const float*)p_kvln, Wv, bv, (float*)p_V,
                             (const float*)p_rope, nullptr, MODE_PLAIN);

    attn_kernel<<<NHH * BB * 64, 256, ATTN_SMEM>>>((const float*)p_Q, (const float*)p_K,
                                                   (const float*)p_V, bt, (float*)p_AO);

    gemm_kernel<<<gg, 256>>>((const float*)p_AO, Wo, bo, out,
                             (const float*)p_rope, (const float*)p_qln, MODE_OUT);
}

// round 6
// speedup vs baseline: 2.3998x; 2.3998x over previous
#include <cuda_runtime.h>
#include <math.h>
#include <stdint.h>

// Problem constants
#define BB   8
#define CC   512
#define NN   4096            // H*W
#define MM   (BB*NN)         // 32768 tokens
#define NHH  8
#define DDIM 64
#define EPSV 1e-5f
#define SCALEV 0.125f        // 64^-0.5

#define MODE_PLAIN 0
#define MODE_ROPE  1
#define MODE_OUT   2

// Scratch (device globals: allocation-free rule).
// Memory is tight in the container: only 5 big buffers, with AO aliasing kvln
// (dead after the V projection).
__device__ float g_big [5][MM*CC];  // 0:qln 1:kvln/AO 2:Q 3:K 4:V
__device__ float g_rope[NN*32*2];   // [n][p][{sin,cos}]
__device__ float g_Wr  [4][CC*CC];  // tf32-rounded weights

// ===========================================================================
// helpers
// ===========================================================================
__device__ __forceinline__ uint32_t smem_u32(const void* p) {
    uint32_t a;
    asm("{ .reg .u64 t; cvta.to.shared.u64 t, %1; cvt.u32.u64 %0, t; }" : "=r"(a) : "l"(p));
    return a;
}
__device__ __forceinline__ float round_tf32(float x) {
    uint32_t r;
    asm("cvt.rna.tf32.f32 %0, %1;" : "=r"(r) : "f"(x));
    return __uint_as_float(r);
}
#define CP_ASYNC16(dst, src) \
    asm volatile("cp.async.cg.shared.global [%0], [%1], 16;" :: "r"(dst), "l"(src))
#define CP_COMMIT() asm volatile("cp.async.commit_group;" ::: "memory")

#define LDMX4(r0, r1, r2, r3, addr) \
    asm volatile("ldmatrix.sync.aligned.m8n8.x4.shared.b16 {%0,%1,%2,%3}, [%4];" \
        : "=r"(r0), "=r"(r1), "=r"(r2), "=r"(r3) : "r"(addr))

#define MMA_TF32(d, a, b0v, b1v) \
    asm volatile("mma.sync.aligned.m16n8k8.row.col.f32.tf32.tf32.f32 " \
        "{%0,%1,%2,%3}, {%4,%5,%6,%7}, {%8,%9}, {%0,%1,%2,%3};" \
        : "+f"((d)[0]), "+f"((d)[1]), "+f"((d)[2]), "+f"((d)[3]) \
        : "r"((a)[0]), "r"((a)[1]), "r"((a)[2]), "r"((a)[3]), "r"(b0v), "r"(b1v))

// SW128 swizzle on a byte offset relative to a 1024B-aligned tile base
#define SWZ(o) ((o) ^ (((o) >> 3) & 0x70))

// ===========================================================================
// LayerNorm over C at each spatial position. NCHW in, (B*N, C) out,
// output rounded to tf32 grid (unbiased rna) for the tensor-core GEMMs.
// ===========================================================================
__global__ void __launch_bounds__(256) ln_kernel(const float* __restrict__ x,
                                                 const float* __restrict__ g,
                                                 const float* __restrict__ bln,
                                                 float* __restrict__ out)
{
    __shared__ float tile[CC][17];
    __shared__ float s_mu[16], s_rs[16];

    int m0   = blockIdx.x * 16;
    int bimg = m0 / NN;
    int n0   = m0 % NN;
    const float* xb = x + (size_t)bimg * CC * NN + n0;

    for (int idx = threadIdx.x; idx < CC * 16; idx += 256) {
        int c = idx >> 4, p = idx & 15;
        tile[c][p] = xb[(size_t)c * NN + p];
    }
    __syncthreads();

    int p = threadIdx.x >> 4;
    int l = threadIdx.x & 15;
    float sum = 0.f, sq = 0.f;
    #pragma unroll
    for (int i = 0; i < 32; i++) {
        float v = tile[l + 16 * i][p];
        sum += v; sq += v * v;
    }
    #pragma unroll
    for (int o = 8; o > 0; o >>= 1) {
        sum += __shfl_xor_sync(0xffffffffu, sum, o);
        sq  += __shfl_xor_sync(0xffffffffu, sq,  o);
    }
    if (l == 0) {
        float mu  = sum * (1.f / 512.f);
        float var = sq * (1.f / 512.f) - mu * mu;
        s_mu[p] = mu;
        s_rs[p] = rsqrtf(var + EPSV);
    }
    __syncthreads();

    for (int idx = threadIdx.x; idx < CC * 16; idx += 256) {
        int pp = idx >> 9, c = idx & 511;
        float v = (tile[c][pp] - s_mu[pp]) * s_rs[pp] * g[c] + bln[c];
        out[(size_t)(m0 + pp) * CC + c] = round_tf32(v);
    }
}

// ===========================================================================
// RoPE table + weight rounding
// ===========================================================================
__global__ void rope_kernel(float* __restrict__ rope)
{
    int idx = blockIdx.x * 256 + threadIdx.x;
    if (idx >= NN * 32) return;
    int n = idx >> 5, pp = idx & 31;
    float inv = 1.f / powf(10000.f, (float)(2 * pp) / 64.f);
    float ang = (float)n * inv;
    rope[idx * 2]     = sinf(ang);
    rope[idx * 2 + 1] = cosf(ang);
}

__global__ void __launch_bounds__(256) roundw_kernel(
    const float* __restrict__ w0, const float* __restrict__ w1,
    const float* __restrict__ w2, const float* __restrict__ w3,
    float* __restrict__ dst)
{
    int idx = blockIdx.x * 256 + threadIdx.x;   // 4*CC*CC threads
    int m = idx >> 18;                           // which matrix (CC*CC = 262144)
    int o = idx & (CC * CC - 1);
    const float* src = (m == 0) ? w0 : (m == 1) ? w1 : (m == 2) ? w2 : w3;
    dst[idx] = round_tf32(src[o]);
}

// ===========================================================================
// tf32 tensor-core GEMM: C[m,n] = sum_k A[m,k]*W[n,k] + bias[n]
// M=32768, N=512, K=512.  CTA 128x256, 8 warps of 64x64, BK=32,
// 4-stage cp.async -> SW128 smem -> ldmatrix.x4 -> mma.sync tf32.
// Epilogue fuses bias / RoPE / residual+NCHW-transpose.
// ===========================================================================
#define BM 128
#define BN 256
#define BK 32
#define KITERS 16
#define STAGES 4
#define STAGE_A (BM * BK * 4)                  // 16384
#define STAGE_B (BN * BK * 4)                  // 32768
#define STAGE_BYTES (STAGE_A + STAGE_B)        // 49152
#define GEMM_SMEM (STAGES * STAGE_BYTES)       // 196608

__global__ void __launch_bounds__(256) gemm_tc(
    const float* __restrict__ A, const float* __restrict__ Wm,
    const float* __restrict__ bias, float* __restrict__ Cout,
    const float* __restrict__ rope, const float* __restrict__ resid,
    int mode)
{
    extern __shared__ char smem[];
    uint32_t sbase = smem_u32(smem);
    int tid  = threadIdx.x;
    int wid  = tid >> 5, lane = tid & 31;
    int wm   = wid & 1,  wn   = wid >> 1;      // 2 x 4 warp grid
    int m0   = blockIdx.y * BM;
    int n0   = blockIdx.x * BN;

    const float* Arow = A  + (size_t)m0 * 512;
    const float* Brow = Wm + (size_t)n0 * 512;

    auto load_stage = [&](int kt, int slot) {
        uint32_t st = sbase + slot * STAGE_BYTES;
        int k0 = kt * BK;
        #pragma unroll
        for (int u = 0; u < 4; u++) {          // A: 128 rows x 128B
            int f = tid + u * 256;
            int r = f >> 3, q = f & 7;
            CP_ASYNC16(st + SWZ((uint32_t)(r * 128 + q * 16)),
                       Arow + (size_t)r * 512 + k0 + q * 4);
        }
        #pragma unroll
        for (int u = 0; u < 8; u++) {          // B: 256 rows x 128B
            int f = tid + u * 256;
            int r = f >> 3, q = f & 7;
            CP_ASYNC16(st + STAGE_A + SWZ((uint32_t)(r * 128 + q * 16)),
                       Brow + (size_t)r * 512 + k0 + q * 4);
        }
        CP_COMMIT();
    };

    float acc[4][8][4];
    #pragma unroll
    for (int mt = 0; mt < 4; mt++)
        #pragma unroll
        for (int nt = 0; nt < 8; nt++)
            #pragma unroll
            for (int j = 0; j < 4; j++) acc[mt][nt][j] = 0.f;

    // per-thread ldmatrix address components
    int a_row  = wm * 64 + (lane & 15);              // + mt*16
    int a_kb   = (lane >> 4) << 4;                   // 0 or 16
    int b_row  = wn * 64 + (lane & 7) + ((lane >> 4) & 1) * 8;   // + np*16
    int b_kb   = ((lane >> 3) & 1) << 4;             // 0 or 16

    load_stage(0, 0);
    load_stage(1, 1);
    load_stage(2, 2);

    for (int kt = 0; kt < KITERS; kt++) {
        int slot = kt & 3;
        if (kt < 14)       asm volatile("cp.async.wait_group 2;" ::: "memory");
        else if (kt == 14) asm volatile("cp.async.wait_group 1;" ::: "memory");
        else               asm volatile("cp.async.wait_group 0;" ::: "memory");
        __syncthreads();

        uint32_t sA = sbase + slot * STAGE_BYTES;
        uint32_t sB = sA + STAGE_A;

        #pragma unroll
        for (int ks = 0; ks < 4; ks++) {
            uint32_t af[4][4], bf[4][4];
            #pragma unroll
            for (int mt = 0; mt < 4; mt++) {
                uint32_t ad = sA + SWZ((uint32_t)((a_row + mt * 16) * 128 + ks * 32 + a_kb));
                LDMX4(af[mt][0], af[mt][1], af[mt][2], af[mt][3], ad);
            }
            #pragma unroll
            for (int np = 0; np < 4; np++) {
                uint32_t bd = sB + SWZ((uint32_t)((b_row + np * 16) * 128 + ks * 32 + b_kb));
                LDMX4(bf[np][0], bf[np][1], bf[np][2], bf[np][3], bd);
            }
            #pragma unroll
            for (int mt = 0; mt < 4; mt++)
                #pragma unroll
                for (int np = 0; np < 4; np++) {
                    MMA_TF32(acc[mt][2 * np],     af[mt], bf[np][0], bf[np][1]);
                    MMA_TF32(acc[mt][2 * np + 1], af[mt], bf[np][2], bf[np][3]);
                }
        }

        if (kt <= 12) load_stage(kt + 3, (kt + 3) & 3);
    }

    // ---------------- epilogue ----------------
    int rbase = m0 + wm * 64 + (lane >> 2);          // + mt*16 (+8)
    int cbase = n0 + wn * 64 + 2 * (lane & 3);       // + nt*8
    int bimg  = m0 >> 12;

    #pragma unroll
    for (int mt = 0; mt < 4; mt++) {
        int r0 = rbase + mt * 16;
        #pragma unroll
        for (int half = 0; half < 2; half++) {
            int r    = r0 + half * 8;
            int npos = r & (NN - 1);
            const float* rp = rope + (size_t)npos * 64;
            #pragma unroll
            for (int nt = 0; nt < 8; nt++) {
                int   c  = cbase + nt * 8;
                float v0 = acc[mt][nt][2 * half]     + bias[c];
                float v1 = acc[mt][nt][2 * half + 1] + bias[c + 1];

                if (mode == MODE_ROPE) {
                    int   p = (c & 63) >> 1;
                    float s = rp[2 * p], co = rp[2 * p + 1];
                    float x0 = v0, x1 = v1;
                    v0 = x0 * co - x1 * s;
                    v1 = x0 * s  + x1 * co;
                }

                if (mode == MODE_OUT) {
                    const float* rr = resid + (size_t)r * 512 + c;
                    v0 += rr[0]; v1 += rr[1];
                    float* ob = Cout + (size_t)bimg * CC * NN + npos;
                    ob[(size_t)c * NN]       = v0;
                    ob[(size_t)(c + 1) * NN] = v1;
                } else {
                    float* op = Cout + (size_t)r * 512 + c;
                    op[0] = v0; op[1] = v1;
                }
            }
        }
    }
}

// ===========================================================================
// Window attention: one block per (head, window). Ws=64, D=64.
// Output rounded to tf32 grid (feeds the O-projection GEMM).
// ===========================================================================
#define ATTN_SMEM (4 * 64 * 68 * 4)

__global__ void __launch_bounds__(256) attn_kernel(
    const float* __restrict__ Q, const float* __restrict__ K,
    const float* __restrict__ V, const float* __restrict__ bt,
    float* __restrict__ O)
{
    extern __shared__ float sm[];
    float* Qs = sm;
    float* Kt = sm + 64 * 68;
    float* Vs = sm + 2 * 64 * 68;
    float* S  = sm + 3 * 64 * 68;
    __shared__ float tb[232];

    int bi  = blockIdx.x;
    int h   = bi >> 9;
    int rem = bi & 511;
    int b   = rem >> 6;
    int hn  = (rem >> 3) & 7;
    int wn  = rem & 7;
    int tid = threadIdx.x;

    for (int t = tid; t < 225; t += 256) tb[t] = bt[t * NHH + h];

    size_t base = ((size_t)b * NN) * CC + (size_t)h * DDIM;

    for (int f = tid; f < 1024; f += 256) {
        int s  = f >> 4, dq = f & 15;
        int wh = s >> 3, ww = s & 7;
        int n  = (hn * 8 + wh) * 64 + wn * 8 + ww;
        size_t ga = base + (size_t)n * CC + dq * 4;
        float4 qv = *(const float4*)(Q + ga);
        *(float4*)&Qs[s * 68 + dq * 4] = qv;
        float4 kv = *(const float4*)(K + ga);
        Kt[(dq * 4 + 0) * 68 + s] = kv.x;
        Kt[(dq * 4 + 1) * 68 + s] = kv.y;
        Kt[(dq * 4 + 2) * 68 + s] = kv.z;
        Kt[(dq * 4 + 3) * 68 + s] = kv.w;
        float4 vv = *(const float4*)(V + ga);
        *(float4*)&Vs[s * 68 + dq * 4] = vv;
    }
    __syncthreads();

    int tc = tid & 15, tr = tid >> 4;
    int r0 = tr * 4, c0 = tc * 4;

    float acc[4][4] = {};
    for (int d = 0; d < 64; d += 4) {
        float4 kf[4];
        #pragma unroll
        for (int u = 0; u < 4; u++) kf[u] = *(const float4*)&Kt[(d + u) * 68 + c0];
        #pragma unroll
        for (int ii = 0; ii < 4; ii++) {
            float4 qf = *(const float4*)&Qs[(r0 + ii) * 68 + d];
            acc[ii][0] += qf.x*kf[0].x + qf.y*kf[1].x + qf.z*kf[2].x + qf.w*kf[3].x;
            acc[ii][1] += qf.x*kf[0].y + qf.y*kf[1].y + qf.z*kf[2].y + qf.w*kf[3].y;
            acc[ii][2] += qf.x*kf[0].z + qf.y*kf[1].z + qf.z*kf[2].z + qf.w*kf[3].z;
            acc[ii][3] += qf.x*kf[0].w + qf.y*kf[1].w + qf.z*kf[2].w + qf.w*kf[3].w;
        }
    }

    #pragma unroll
    for (int ii = 0; ii < 4; ii++) {
        int i = r0 + ii; int ih = i >> 3, iw = i & 7;
        #pragma unroll
        for (int jj = 0; jj < 4; jj++) {
            int j = c0 + jj; int jh = j >> 3, jw = j & 7;
            int ridx = (ih - jh + 7) * 15 + (iw - jw + 7);
            S[i * 68 + j] = acc[ii][jj] * SCALEV + tb[ridx];
        }
    }
    __syncthreads();

    {
        int r = tid >> 2, qg = tid & 3;
        float* row = S + r * 68 + qg * 16;
        float mx = -INFINITY;
        #pragma unroll
        for (int j = 0; j < 16; j++) mx = fmaxf(mx, row[j]);
        mx = fmaxf(mx, __shfl_xor_sync(0xffffffffu, mx, 1));
        mx = fmaxf(mx, __shfl_xor_sync(0xffffffffu, mx, 2));
        float e[16], sum = 0.f;
        #pragma unroll
        for (int j = 0; j < 16; j++) { e[j] = expf(row[j] - mx); sum += e[j]; }
        sum += __shfl_xor_sync(0xffffffffu, sum, 1);
        sum += __shfl_xor_sync(0xffffffffu, sum, 2);
        float inv = 1.f / sum;
        #pragma unroll
        for (int j = 0; j < 16; j++) row[j] = e[j] * inv;
    }
    __syncthreads();

    float oacc[4][4] = {};
    for (int j = 0; j < 64; j += 4) {
        float4 vf[4];
        #pragma unroll
        for (int u = 0; u < 4; u++) vf[u] = *(const float4*)&Vs[(j + u) * 68 + c0];
        #pragma unroll
        for (int ii = 0; ii < 4; ii++) {
            float4 pf = *(const float4*)&S[(r0 + ii) * 68 + j];
            oacc[ii][0] += pf.x*vf[0].x + pf.y*vf[1].x + pf.z*vf[2].x + pf.w*vf[3].x;
            oacc[ii][1] += pf.x*vf[0].y + pf.y*vf[1].y + pf.z*vf[2].y + pf.w*vf[3].y;
            oacc[ii][2] += pf.x*vf[0].z + pf.y*vf[1].z + pf.z*vf[2].z + pf.w*vf[3].z;
            oacc[ii][3] += pf.x*vf[0].w + pf.y*vf[1].w + pf.z*vf[2].w + pf.w*vf[3].w;
        }
    }

    #pragma unroll
    for (int ii = 0; ii < 4; ii++) {
        int s  = r0 + ii;
        int wh = s >> 3, ww = s & 7;
        int n  = (hn * 8 + wh) * 64 + wn * 8 + ww;
        *(float4*)(O + base + (size_t)n * CC + c0) =
            make_float4(round_tf32(oacc[ii][0]), round_tf32(oacc[ii][1]),
                        round_tf32(oacc[ii][2]), round_tf32(oacc[ii][3]));
    }
}

// ===========================================================================
extern "C" void kernel_launch(void* const* d_in, const int* in_sizes, int n_in,
                              void* d_out, int out_size)
{
    const float* q    = (const float*)d_in[0];
    const float* kv   = (const float*)d_in[1];
    const float* g_q  = (const float*)d_in[2];
    const float* b_q  = (const float*)d_in[3];
    const float* g_kv = (const float*)d_in[4];
    const float* b_kv = (const float*)d_in[5];
    const float* Wq   = (const float*)d_in[6];
    const float* bq   = (const float*)d_in[7];
    const float* Wk   = (const float*)d_in[8];
    const float* bk   = (const float*)d_in[9];
    const float* Wv   = (const float*)d_in[10];
    const float* bv   = (const float*)d_in[11];
    const float* Wo   = (const float*)d_in[12];
    const float* bo   = (const float*)d_in[13];
    const float* bt   = (const float*)d_in[14];
    float* out = (float*)d_out;

    void *p_big, *p_rope, *p_Wr;
    cudaGetSymbolAddress(&p_big,  g_big);
    cudaGetSymbolAddress(&p_rope, g_rope);
    cudaGetSymbolAddress(&p_Wr,   g_Wr);

    float* qln  = (float*)p_big + 0 * (size_t)MM * CC;
    float* kvln = (float*)p_big + 1 * (size_t)MM * CC;
    float* Qb   = (float*)p_big + 2 * (size_t)MM * CC;
    float* Kb   = (float*)p_big + 3 * (size_t)MM * CC;
    float* Vb   = (float*)p_big + 4 * (size_t)MM * CC;
    float* AO   = kvln;                 // aliased: kvln dead after V GEMM
    float* Wr   = (float*)p_Wr;
    float* rope = (float*)p_rope;

    cudaFuncSetAttribute(attn_kernel, cudaFuncAttributeMaxDynamicSharedMemorySize, ATTN_SMEM);
    cudaFuncSetAttribute(gemm_tc,     cudaFuncAttributeMaxDynamicSharedMemorySize, GEMM_SMEM);

    ln_kernel<<<MM / 16, 256>>>(q,  g_q,  b_q,  qln);
    ln_kernel<<<MM / 16, 256>>>(kv, g_kv, b_kv, kvln);
    rope_kernel<<<(NN * 32 + 255) / 256, 256>>>(rope);
    roundw_kernel<<<4 * CC * CC / 256, 256>>>(Wq, Wk, Wv, Wo, Wr);

    dim3 gg(2, 256);
    gemm_tc<<<gg, 256, GEMM_SMEM>>>(qln,  Wr + 0 * CC * CC, bq, Qb,
                                    rope, nullptr, MODE_ROPE);
    gemm_tc<<<gg, 256, GEMM_SMEM>>>(kvln, Wr + 1 * CC * CC, bk, Kb,
                                    rope, nullptr, MODE_ROPE);
    gemm_tc<<<gg, 256, GEMM_SMEM>>>(kvln, Wr + 2 * CC * CC, bv, Vb,
                                    rope, nullptr, MODE_PLAIN);

    attn_kernel<<<NHH * BB * 64, 256, ATTN_SMEM>>>(Qb, Kb, Vb, bt, AO);

    gemm_tc<<<gg, 256, GEMM_SMEM>>>(AO, Wr + 3 * CC * CC, bo, out,
                                    rope, qln, MODE_OUT);
}